// round 2
// baseline (speedup 1.0000x reference)
#include <cuda_runtime.h>
#include <math.h>
#include <float.h>

#define BATCH 2
#define NTOK  8000
#define CDIM  512
#define NSR   1000
#define NHEADS 8
#define HD    64

// ---------------- scratch (device globals: no allocation allowed) ----------------
__device__ float g_xr[BATCH * NSR * CDIM];          // 4 MB
__device__ float g_kv[BATCH * NSR * 2 * CDIM];      // 8 MB  (cols 0..511 = K, 512..1023 = V)
__device__ float g_q [BATCH * NTOK * CDIM];         // 33 MB
__device__ float g_o [BATCH * NTOK * CDIM];         // 33 MB
__device__ float g_y [BATCH * NTOK * CDIM];         // 33 MB

// ---------------- kernel 1: depthwise conv3d (3,s2,p1) + bias + LayerNorm ----------------
__global__ void __launch_bounds__(256) conv_ln_kernel(
    const float* __restrict__ x, const float* __restrict__ srw,
    const float* __restrict__ srb, const float* __restrict__ g,
    const float* __restrict__ beta, float* __restrict__ xr)
{
    int bp = blockIdx.x;
    int b = bp / NSR;
    int opos = bp % NSR;
    int od = opos / 100, oh = (opos / 10) % 10, ow = opos % 10;

    __shared__ float vals[CDIM];
    __shared__ float red[18];

    float loc[2];
#pragma unroll
    for (int ci = 0; ci < 2; ci++) {
        int c = threadIdx.x + ci * 256;
        float acc = srb[c];
#pragma unroll
        for (int kd = 0; kd < 3; kd++) {
            int id = od * 2 - 1 + kd;
            if ((unsigned)id >= 20u) continue;
#pragma unroll
            for (int kh = 0; kh < 3; kh++) {
                int ih = oh * 2 - 1 + kh;
                if ((unsigned)ih >= 20u) continue;
#pragma unroll
                for (int kw = 0; kw < 3; kw++) {
                    int iw = ow * 2 - 1 + kw;
                    if ((unsigned)iw >= 20u) continue;
                    int n = id * 400 + ih * 20 + iw;
                    acc += x[((size_t)b * NTOK + n) * CDIM + c] *
                           srw[c * 27 + kd * 9 + kh * 3 + kw];
                }
            }
        }
        vals[c] = acc;
        loc[ci] = acc;
    }
    float s  = loc[0] + loc[1];
    float sq = loc[0] * loc[0] + loc[1] * loc[1];
#pragma unroll
    for (int o2 = 16; o2 > 0; o2 >>= 1) {
        s  += __shfl_down_sync(0xffffffffu, s,  o2);
        sq += __shfl_down_sync(0xffffffffu, sq, o2);
    }
    int w = threadIdx.x >> 5;
    if ((threadIdx.x & 31) == 0) { red[w] = s; red[8 + w] = sq; }
    __syncthreads();
    if (threadIdx.x == 0) {
        float a = 0.f, b2 = 0.f;
        for (int i = 0; i < 8; i++) { a += red[i]; b2 += red[8 + i]; }
        red[16] = a; red[17] = b2;
    }
    __syncthreads();
    float mean = red[16] * (1.f / CDIM);
    float var  = red[17] * (1.f / CDIM) - mean * mean;
    float inv  = rsqrtf(var + 1e-6f);
#pragma unroll
    for (int ci = 0; ci < 2; ci++) {
        int c = threadIdx.x + ci * 256;
        xr[((size_t)b * NSR + opos) * CDIM + c] = (vals[c] - mean) * inv * g[c] + beta[c];
    }
}

// ---------------- generic GEMM + bias: C[M,N] = A[M,K] @ B[K,N] + bias ----------------
// 128x128 block tile, BK=16, 256 threads, 8x8 micro-tile
__global__ void __launch_bounds__(256) gemm_bias_kernel(
    const float* __restrict__ A, const float* __restrict__ B,
    const float* __restrict__ bias, float* __restrict__ C,
    int M, int N, int K)
{
    __shared__ float As[16][128];
    __shared__ float Bs[16][128];

    int tid = threadIdx.x;
    int tx = tid & 15, ty = tid >> 4;
    int rowBase = blockIdx.y * 128, colBase = blockIdx.x * 128;

    float acc[8][8];
#pragma unroll
    for (int i = 0; i < 8; i++)
#pragma unroll
        for (int j = 0; j < 8; j++) acc[i][j] = 0.f;

    for (int kt = 0; kt < K; kt += 16) {
#pragma unroll
        for (int l = 0; l < 2; l++) {
            int idx = tid + l * 256;
            int r = idx >> 2, kc = (idx & 3) << 2;
            int gr = rowBase + r;
            float4 v = make_float4(0.f, 0.f, 0.f, 0.f);
            if (gr < M) v = *(const float4*)&A[(size_t)gr * K + kt + kc];
            As[kc + 0][r] = v.x; As[kc + 1][r] = v.y;
            As[kc + 2][r] = v.z; As[kc + 3][r] = v.w;
        }
#pragma unroll
        for (int l = 0; l < 2; l++) {
            int idx = tid + l * 256;
            int kr = idx >> 5, cc = (idx & 31) << 2;
            *(float4*)&Bs[kr][cc] = *(const float4*)&B[(size_t)(kt + kr) * N + colBase + cc];
        }
        __syncthreads();
#pragma unroll
        for (int k = 0; k < 16; k++) {
            float a[8], bb[8];
            *(float4*)&a[0]  = *(float4*)&As[k][ty * 8];
            *(float4*)&a[4]  = *(float4*)&As[k][ty * 8 + 4];
            *(float4*)&bb[0] = *(float4*)&Bs[k][tx * 8];
            *(float4*)&bb[4] = *(float4*)&Bs[k][tx * 8 + 4];
#pragma unroll
            for (int i = 0; i < 8; i++)
#pragma unroll
                for (int j = 0; j < 8; j++) acc[i][j] += a[i] * bb[j];
        }
        __syncthreads();
    }
#pragma unroll
    for (int i = 0; i < 8; i++) {
        int gr = rowBase + ty * 8 + i;
        if (gr < M) {
#pragma unroll
            for (int j = 0; j < 8; j++) {
                int gc = colBase + tx * 8 + j;
                C[(size_t)gr * N + gc] = acc[i][j] + bias[gc];
            }
        }
    }
}

// ---------------- kernel 4: flash attention (fp32) ----------------
// grid: (N/64, B*h). block 256. Tiles: Q 64x64, K 64x64, V 64x64, P 64x64 in smem.
#define ATT_STRIDE 68
#define ATT_SMEM_FLOATS (4 * 64 * ATT_STRIDE + 3 * 64)
#define ATT_SMEM_BYTES  (ATT_SMEM_FLOATS * 4)

__global__ void __launch_bounds__(256) attn_kernel(
    const float* __restrict__ q, const float* __restrict__ kv,
    float* __restrict__ o)
{
    extern __shared__ float sm[];
    float (*Qs)[ATT_STRIDE] = (float(*)[ATT_STRIDE])(sm);
    float (*Ks)[ATT_STRIDE] = (float(*)[ATT_STRIDE])(sm + 64 * ATT_STRIDE);
    float (*Vs)[ATT_STRIDE] = (float(*)[ATT_STRIDE])(sm + 2 * 64 * ATT_STRIDE);
    float (*Ps)[ATT_STRIDE] = (float(*)[ATT_STRIDE])(sm + 3 * 64 * ATT_STRIDE);
    float* rowM = sm + 4 * 64 * ATT_STRIDE;
    float* rowL = rowM + 64;
    float* rowC = rowL + 64;

    int tid = threadIdx.x;
    int tx = tid & 15, ty = tid >> 4;
    int bh = blockIdx.y;
    int b = bh >> 3, h = bh & 7;
    int qbase = blockIdx.x * 64;
    size_t qoff   = ((size_t)b * NTOK + qbase) * CDIM + h * HD;
    size_t kvbase = (size_t)b * NSR * 1024 + h * HD;

    // load Q tile (64 rows x 64 dims)
#pragma unroll
    for (int l = 0; l < 4; l++) {
        int idx = tid + l * 256;
        int i = idx >> 4, d4 = (idx & 15) << 2;
        *(float4*)&Qs[i][d4] = *(const float4*)&q[qoff + (size_t)i * CDIM + d4];
    }
    if (tid < 64) { rowM[tid] = -FLT_MAX; rowL[tid] = 0.f; }

    float acc[4][4];
#pragma unroll
    for (int i = 0; i < 4; i++)
#pragma unroll
        for (int j = 0; j < 4; j++) acc[i][j] = 0.f;

    const float scale = 0.125f;  // 64^-0.5

    for (int kb = 0; kb < NSR; kb += 64) {
        __syncthreads();  // protect Ks/Vs/Ps from prior-iteration readers
#pragma unroll
        for (int l = 0; l < 4; l++) {
            int idx = tid + l * 256;
            int m = idx >> 4, d4 = (idx & 15) << 2;
            int gm = kb + m;
            float4 kf = make_float4(0.f, 0.f, 0.f, 0.f);
            float4 vf = make_float4(0.f, 0.f, 0.f, 0.f);
            if (gm < NSR) {
                kf = *(const float4*)&kv[kvbase + (size_t)gm * 1024 + d4];
                vf = *(const float4*)&kv[kvbase + (size_t)gm * 1024 + 512 + d4];
            }
            *(float4*)&Ks[m][d4] = kf;
            *(float4*)&Vs[m][d4] = vf;
        }
        __syncthreads();

        // S = Q @ K^T  (4x4 micro-tile, k unrolled by 4 via float4 fragments)
        float s4[4][4];
#pragma unroll
        for (int i = 0; i < 4; i++)
#pragma unroll
            for (int j = 0; j < 4; j++) s4[i][j] = 0.f;

#pragma unroll
        for (int k4 = 0; k4 < 64; k4 += 4) {
            float4 qf[4], kf[4];
#pragma unroll
            for (int i = 0; i < 4; i++) qf[i] = *(float4*)&Qs[ty * 4 + i][k4];
#pragma unroll
            for (int j = 0; j < 4; j++) kf[j] = *(float4*)&Ks[tx * 4 + j][k4];
#pragma unroll
            for (int i = 0; i < 4; i++)
#pragma unroll
                for (int j = 0; j < 4; j++)
                    s4[i][j] += qf[i].x * kf[j].x + qf[i].y * kf[j].y +
                                qf[i].z * kf[j].z + qf[i].w * kf[j].w;
        }
#pragma unroll
        for (int i = 0; i < 4; i++)
#pragma unroll
            for (int j = 0; j < 4; j++)
                Ps[ty * 4 + i][tx * 4 + j] = s4[i][j] * scale;
        __syncthreads();

        // online softmax row pass (one thread per row)
        if (tid < 64) {
            int valid = NSR - kb; if (valid > 64) valid = 64;
            float mOld = rowM[tid];
            float tm = -FLT_MAX;
            for (int j = 0; j < valid; j++) tm = fmaxf(tm, Ps[tid][j]);
            float nm = fmaxf(mOld, tm);
            float corr = __expf(mOld - nm);   // first tile: exp(-inf) = 0
            float ssum = 0.f;
            for (int j = 0; j < 64; j++) {
                float p = (j < valid) ? __expf(Ps[tid][j] - nm) : 0.f;
                Ps[tid][j] = p;
                ssum += p;
            }
            rowL[tid] = rowL[tid] * corr + ssum;
            rowM[tid] = nm;
            rowC[tid] = corr;
        }
        __syncthreads();

        // rescale accumulator, then O += P @ V
#pragma unroll
        for (int i = 0; i < 4; i++) {
            float cr = rowC[ty * 4 + i];
#pragma unroll
            for (int j = 0; j < 4; j++) acc[i][j] *= cr;
        }
#pragma unroll
        for (int m4 = 0; m4 < 64; m4 += 4) {
            float pfa[4][4];
            float vfa[4][4];
#pragma unroll
            for (int i = 0; i < 4; i++) {
                float4 p4 = *(float4*)&Ps[ty * 4 + i][m4];
                pfa[i][0] = p4.x; pfa[i][1] = p4.y; pfa[i][2] = p4.z; pfa[i][3] = p4.w;
            }
#pragma unroll
            for (int u = 0; u < 4; u++) {
                float4 v4 = *(float4*)&Vs[m4 + u][tx * 4];
                vfa[u][0] = v4.x; vfa[u][1] = v4.y; vfa[u][2] = v4.z; vfa[u][3] = v4.w;
            }
#pragma unroll
            for (int i = 0; i < 4; i++)
#pragma unroll
                for (int u = 0; u < 4; u++)
#pragma unroll
                    for (int j = 0; j < 4; j++)
                        acc[i][j] += pfa[i][u] * vfa[u][j];
        }
    }

    // finalize
#pragma unroll
    for (int i = 0; i < 4; i++) {
        int r = ty * 4 + i;
        float invl = 1.f / rowL[r];
        int gn = qbase + r;
#pragma unroll
        for (int j = 0; j < 4; j++)
            o[((size_t)b * NTOK + gn) * CDIM + h * HD + tx * 4 + j] = acc[i][j] * invl;
    }
}

// ---------------- kernel 5: trilinear upsample of V + LayerNorm + add o ----------------
__global__ void __launch_bounds__(256) ups_ln_add_kernel(
    const float* __restrict__ kv, const float* __restrict__ ob,
    const float* __restrict__ g, const float* __restrict__ beta,
    float* __restrict__ y)
{
    int bn = blockIdx.x;
    int b = bn / NTOK, n = bn % NTOK;
    int d = n / 400, hh = (n / 20) % 20, ww = n % 20;

    // half-pixel trilinear, edge-clamped (matches jax.image.resize weight renorm)
    float sd = d  * 0.5f - 0.25f; int fd = (int)floorf(sd); float wdz = sd - (float)fd;
    float sh = hh * 0.5f - 0.25f; int fh = (int)floorf(sh); float why = sh - (float)fh;
    float sw = ww * 0.5f - 0.25f; int fw = (int)floorf(sw); float wwx = sw - (float)fw;
    int dz0 = fd < 0 ? 0 : fd;        int dz1 = (fd + 1) > 9 ? 9 : (fd + 1);
    int hy0 = fh < 0 ? 0 : fh;        int hy1 = (fh + 1) > 9 ? 9 : (fh + 1);
    int wx0 = fw < 0 ? 0 : fw;        int wx1 = (fw + 1) > 9 ? 9 : (fw + 1);

    int   midx[8];
    float wt8[8];
    {
        int zzv[2] = {dz0, dz1};  float wzv[2] = {1.f - wdz, wdz};
        int yyv[2] = {hy0, hy1};  float wyv[2] = {1.f - why, why};
        int xxv[2] = {wx0, wx1};  float wxv[2] = {1.f - wwx, wwx};
        int t = 0;
#pragma unroll
        for (int a = 0; a < 2; a++)
#pragma unroll
            for (int b2 = 0; b2 < 2; b2++)
#pragma unroll
                for (int c2 = 0; c2 < 2; c2++) {
                    midx[t] = zzv[a] * 100 + yyv[b2] * 10 + xxv[c2];
                    wt8[t]  = wzv[a] * wyv[b2] * wxv[c2];
                    t++;
                }
    }

    __shared__ float vals[CDIM];
    __shared__ float red[18];
    size_t kvb = (size_t)b * NSR * 1024 + 512;   // V half

    float loc[2];
#pragma unroll
    for (int ci = 0; ci < 2; ci++) {
        int c = threadIdx.x + ci * 256;
        float acc = 0.f;
#pragma unroll
        for (int t = 0; t < 8; t++)
            acc += wt8[t] * kv[kvb + (size_t)midx[t] * 1024 + c];
        vals[c] = acc;
        loc[ci] = acc;
    }
    float s  = loc[0] + loc[1];
    float sq = loc[0] * loc[0] + loc[1] * loc[1];
#pragma unroll
    for (int o2 = 16; o2 > 0; o2 >>= 1) {
        s  += __shfl_down_sync(0xffffffffu, s,  o2);
        sq += __shfl_down_sync(0xffffffffu, sq, o2);
    }
    int w = threadIdx.x >> 5;
    if ((threadIdx.x & 31) == 0) { red[w] = s; red[8 + w] = sq; }
    __syncthreads();
    if (threadIdx.x == 0) {
        float a = 0.f, b2 = 0.f;
        for (int i = 0; i < 8; i++) { a += red[i]; b2 += red[8 + i]; }
        red[16] = a; red[17] = b2;
    }
    __syncthreads();
    float mean = red[16] * (1.f / CDIM);
    float var  = red[17] * (1.f / CDIM) - mean * mean;
    float inv  = rsqrtf(var + 1e-6f);
#pragma unroll
    for (int ci = 0; ci < 2; ci++) {
        int c = threadIdx.x + ci * 256;
        size_t oidx = ((size_t)b * NTOK + n) * CDIM + c;
        float idn = (vals[c] - mean) * inv * g[c] + beta[c];
        y[oidx] = ob[oidx] + idn;
    }
}

// ---------------- launch ----------------
extern "C" void kernel_launch(void* const* d_in, const int* in_sizes, int n_in,
                              void* d_out, int out_size)
{
    const float* x      = (const float*)d_in[0];
    const float* Wq     = (const float*)d_in[1];
    const float* bq     = (const float*)d_in[2];
    const float* Wkv    = (const float*)d_in[3];
    const float* bkv    = (const float*)d_in[4];
    const float* srw    = (const float*)d_in[5];
    const float* srb    = (const float*)d_in[6];
    const float* srg    = (const float*)d_in[7];
    const float* srbeta = (const float*)d_in[8];
    const float* upg    = (const float*)d_in[9];
    const float* upbeta = (const float*)d_in[10];
    const float* Wp     = (const float*)d_in[11];
    const float* bp     = (const float*)d_in[12];
    float* out = (float*)d_out;

    float *xr, *kvb, *qb, *ob, *yb;
    cudaGetSymbolAddress((void**)&xr,  g_xr);
    cudaGetSymbolAddress((void**)&kvb, g_kv);
    cudaGetSymbolAddress((void**)&qb,  g_q);
    cudaGetSymbolAddress((void**)&ob,  g_o);
    cudaGetSymbolAddress((void**)&yb,  g_y);

    cudaFuncSetAttribute(attn_kernel, cudaFuncAttributeMaxDynamicSharedMemorySize,
                         ATT_SMEM_BYTES);

    // 1. conv + LN -> xr
    conv_ln_kernel<<<BATCH * NSR, 256>>>(x, srw, srb, srg, srbeta, xr);

    // 2. kv = xr @ Wkv + bkv   (2000 x 1024 x 512)
    gemm_bias_kernel<<<dim3(1024 / 128, (BATCH * NSR + 127) / 128), 256>>>(
        xr, Wkv, bkv, kvb, BATCH * NSR, 1024, CDIM);

    // 3. q = x @ Wq + bq       (16000 x 512 x 512)
    gemm_bias_kernel<<<dim3(CDIM / 128, (BATCH * NTOK) / 128), 256>>>(
        x, Wq, bq, qb, BATCH * NTOK, CDIM, CDIM);

    // 4. attention -> o
    attn_kernel<<<dim3(NTOK / 64, BATCH * NHEADS), 256, ATT_SMEM_BYTES>>>(qb, kvb, ob);

    // 5. upsample(V) + LN + add o -> y
    ups_ln_add_kernel<<<BATCH * NTOK, 256>>>(kvb, ob, upg, upbeta, yb);

    // 6. out = y @ Wp + bp     (16000 x 512 x 512)
    gemm_bias_kernel<<<dim3(CDIM / 128, (BATCH * NTOK) / 128), 256>>>(
        yb, Wp, bp, out, BATCH * NTOK, CDIM, CDIM);
}

// round 4
// speedup vs baseline: 1.1381x; 1.1381x over previous
#include <cuda_runtime.h>
#include <cuda_bf16.h>
#include <math.h>
#include <float.h>
#include <stdint.h>

#define BATCH 2
#define NTOK  8000
#define CDIM  512
#define NSR   1000
#define NHEADS 8
#define HD    64

__device__ float g_kv[BATCH * NSR * 2 * CDIM];
__device__ float g_q [BATCH * NTOK * CDIM];
__device__ float g_o [BATCH * NTOK * CDIM];
__device__ __nv_bfloat16 g_xh [BATCH * NTOK * CDIM];
__device__ __nv_bfloat16 g_xl [BATCH * NTOK * CDIM];
__device__ __nv_bfloat16 g_yh [BATCH * NTOK * CDIM];
__device__ __nv_bfloat16 g_yl [BATCH * NTOK * CDIM];
__device__ __nv_bfloat16 g_xrh[BATCH * NSR * CDIM];
__device__ __nv_bfloat16 g_xrl[BATCH * NSR * CDIM];
__device__ __nv_bfloat16 g_wqt_h [CDIM * CDIM];
__device__ __nv_bfloat16 g_wqt_l [CDIM * CDIM];
__device__ __nv_bfloat16 g_wkvt_h[2 * CDIM * CDIM];
__device__ __nv_bfloat16 g_wkvt_l[2 * CDIM * CDIM];
__device__ __nv_bfloat16 g_wpt_h [CDIM * CDIM];
__device__ __nv_bfloat16 g_wpt_l [CDIM * CDIM];

// ---------------- split fp32 -> bf16 hi/lo ----------------
__global__ void __launch_bounds__(256) split_kernel(
    const float* __restrict__ s, __nv_bfloat16* __restrict__ h,
    __nv_bfloat16* __restrict__ l, int n)
{
    int i = blockIdx.x * 256 + threadIdx.x;
    if (i < n) {
        float v = s[i];
        __nv_bfloat16 hh = __float2bfloat16(v);
        h[i] = hh;
        l[i] = __float2bfloat16(v - __bfloat162float(hh));
    }
}

// ---------------- transpose + split W[K][N] -> T[N][K] bf16 hi/lo ----------------
__global__ void __launch_bounds__(256) wsplit_t_kernel(
    const float* __restrict__ W, __nv_bfloat16* __restrict__ Th,
    __nv_bfloat16* __restrict__ Tl, int K, int N)
{
    __shared__ float t[32][33];
    int tx = threadIdx.x & 31, ty = threadIdx.x >> 5;
    int nb = blockIdx.x * 32, kb = blockIdx.y * 32;
#pragma unroll
    for (int i = ty; i < 32; i += 8)
        t[i][tx] = W[(size_t)(kb + i) * N + nb + tx];
    __syncthreads();
#pragma unroll
    for (int i = ty; i < 32; i += 8) {
        float v = t[tx][i];
        __nv_bfloat16 hh = __float2bfloat16(v);
        Th[(size_t)(nb + i) * K + kb + tx] = hh;
        Tl[(size_t)(nb + i) * K + kb + tx] = __float2bfloat16(v - __bfloat162float(hh));
    }
}

// ---------------- conv3d depthwise (3,s2,p1) + bias + LN -> bf16 hi/lo ----------------
__global__ void __launch_bounds__(256) conv_ln_kernel(
    const float* __restrict__ x, const float* __restrict__ srw,
    const float* __restrict__ srb, const float* __restrict__ g,
    const float* __restrict__ beta,
    __nv_bfloat16* __restrict__ xrh, __nv_bfloat16* __restrict__ xrl)
{
    int bp = blockIdx.x;
    int b = bp / NSR, opos = bp % NSR;
    int od = opos / 100, oh = (opos / 10) % 10, ow = opos % 10;
    __shared__ float vals[CDIM];
    __shared__ float red[18];
    float loc[2];
#pragma unroll
    for (int ci = 0; ci < 2; ci++) {
        int c = threadIdx.x + ci * 256;
        float acc = srb[c];
#pragma unroll
        for (int kd = 0; kd < 3; kd++) {
            int id = od * 2 - 1 + kd;
            if ((unsigned)id >= 20u) continue;
#pragma unroll
            for (int kh = 0; kh < 3; kh++) {
                int ih = oh * 2 - 1 + kh;
                if ((unsigned)ih >= 20u) continue;
#pragma unroll
                for (int kw = 0; kw < 3; kw++) {
                    int iw = ow * 2 - 1 + kw;
                    if ((unsigned)iw >= 20u) continue;
                    acc += x[((size_t)b * NTOK + id * 400 + ih * 20 + iw) * CDIM + c] *
                           srw[c * 27 + kd * 9 + kh * 3 + kw];
                }
            }
        }
        vals[c] = acc; loc[ci] = acc;
    }
    float s = loc[0] + loc[1], sq = loc[0] * loc[0] + loc[1] * loc[1];
#pragma unroll
    for (int o2 = 16; o2 > 0; o2 >>= 1) {
        s  += __shfl_down_sync(0xffffffffu, s,  o2);
        sq += __shfl_down_sync(0xffffffffu, sq, o2);
    }
    int w = threadIdx.x >> 5;
    if ((threadIdx.x & 31) == 0) { red[w] = s; red[8 + w] = sq; }
    __syncthreads();
    if (threadIdx.x == 0) {
        float a = 0.f, b2 = 0.f;
        for (int i = 0; i < 8; i++) { a += red[i]; b2 += red[8 + i]; }
        red[16] = a; red[17] = b2;
    }
    __syncthreads();
    float mean = red[16] * (1.f / CDIM);
    float var  = red[17] * (1.f / CDIM) - mean * mean;
    float inv  = rsqrtf(var + 1e-6f);
#pragma unroll
    for (int ci = 0; ci < 2; ci++) {
        int c = threadIdx.x + ci * 256;
        float v = (vals[c] - mean) * inv * g[c] + beta[c];
        size_t idx = ((size_t)b * NSR + opos) * CDIM + c;
        __nv_bfloat16 hh = __float2bfloat16(v);
        xrh[idx] = hh;
        xrl[idx] = __float2bfloat16(v - __bfloat162float(hh));
    }
}

// ---------------- mma.sync helpers ----------------
__device__ __forceinline__ void ldsm4(uint32_t& r0, uint32_t& r1, uint32_t& r2, uint32_t& r3,
                                      uint32_t addr)
{
    asm volatile("ldmatrix.sync.aligned.m8n8.x4.shared.b16 {%0,%1,%2,%3}, [%4];"
                 : "=r"(r0), "=r"(r1), "=r"(r2), "=r"(r3) : "r"(addr));
}
__device__ __forceinline__ void mma16816(float* c, const uint32_t* a, const uint32_t* b)
{
    asm volatile("mma.sync.aligned.m16n8k16.row.col.f32.bf16.bf16.f32 "
                 "{%0,%1,%2,%3}, {%4,%5,%6,%7}, {%8,%9}, {%0,%1,%2,%3};"
                 : "+f"(c[0]), "+f"(c[1]), "+f"(c[2]), "+f"(c[3])
                 : "r"(a[0]), "r"(a[1]), "r"(a[2]), "r"(a[3]), "r"(b[0]), "r"(b[1]));
}

// ---------------- tensor-core GEMM: C[M,N] = (Ah+Al)[M,512] @ (Bh+Bl)[N,512]^T + bias ----------------
// 128x128 tile, BK=32, 8 warps (2x4), warp tile 64x32, 3-term bf16 split.
#define SMS 40   // smem row stride in bf16 (80 bytes): conflict-free ldmatrix phases
__global__ void __launch_bounds__(256) gemm_mma_kernel(
    const __nv_bfloat16* __restrict__ Ah, const __nv_bfloat16* __restrict__ Al,
    const __nv_bfloat16* __restrict__ Bh, const __nv_bfloat16* __restrict__ Bl,
    const float* __restrict__ bias, float* __restrict__ C, int M, int N)
{
    __shared__ __nv_bfloat16 sAh[128 * SMS], sAl[128 * SMS], sBh[128 * SMS], sBl[128 * SMS];

    int tid = threadIdx.x, wid = tid >> 5, lane = tid & 31;
    int wr = wid >> 2, wc = wid & 3;               // 2 x 4 warps
    int rowBase = blockIdx.y * 128, colBase = blockIdx.x * 128;

    float acc[4][4][4];
#pragma unroll
    for (int i = 0; i < 4; i++)
#pragma unroll
        for (int j = 0; j < 4; j++)
#pragma unroll
            for (int k = 0; k < 4; k++) acc[i][j][k] = 0.f;

    uint32_t aBaseH = (uint32_t)__cvta_generic_to_shared(sAh);
    uint32_t aBaseL = (uint32_t)__cvta_generic_to_shared(sAl);
    uint32_t bBaseH = (uint32_t)__cvta_generic_to_shared(sBh);
    uint32_t bBaseL = (uint32_t)__cvta_generic_to_shared(sBl);

    for (int k0 = 0; k0 < 512; k0 += 32) {
        __syncthreads();
        // load 4 tiles of 128 rows x 32 bf16 (each row = 4 x 16B)
#pragma unroll
        for (int it = 0; it < 2; it++) {
            int idx = tid + it * 256;            // 0..511
            int r = idx >> 2, c = idx & 3;       // c in 16B units (8 bf16)
            int ar = rowBase + r; if (ar > M - 1) ar = M - 1;
            int br = colBase + r;
            size_t aoff = (size_t)ar * 512 + k0 + c * 8;
            size_t boff = (size_t)br * 512 + k0 + c * 8;
            int soff = r * SMS + c * 8;
            *(uint4*)&sAh[soff] = *(const uint4*)&Ah[aoff];
            *(uint4*)&sAl[soff] = *(const uint4*)&Al[aoff];
            *(uint4*)&sBh[soff] = *(const uint4*)&Bh[boff];
            *(uint4*)&sBl[soff] = *(const uint4*)&Bl[boff];
        }
        __syncthreads();

#pragma unroll
        for (int ks = 0; ks < 32; ks += 16) {
            // A fragment addresses: row = wr*64 + mf*16 + (lane&15); khalf = (lane>>4)*8
            uint32_t aoffs = (uint32_t)(((wr * 64 + (lane & 15)) * SMS + ks + ((lane >> 4) << 3)) * 2);
            // B fragment addresses (2 n-frags per ldmatrix.x4):
            // n = wc*32 + nfp*16 + ((lane>>4)<<3) + (lane&7); khalf = ((lane>>3)&1)*8
            uint32_t boffs = (uint32_t)(((wc * 32 + ((lane >> 4) << 3) + (lane & 7)) * SMS + ks + (((lane >> 3) & 1) << 3)) * 2);

            uint32_t ah[4][4], al[4][4];
#pragma unroll
            for (int mf = 0; mf < 4; mf++) {
                uint32_t ao = aoffs + (uint32_t)(mf * 16 * SMS * 2);
                ldsm4(ah[mf][0], ah[mf][1], ah[mf][2], ah[mf][3], aBaseH + ao);
                ldsm4(al[mf][0], al[mf][1], al[mf][2], al[mf][3], aBaseL + ao);
            }
            uint32_t bh[4][2], bl[4][2];
#pragma unroll
            for (int np = 0; np < 2; np++) {
                uint32_t bo = boffs + (uint32_t)(np * 16 * SMS * 2);
                ldsm4(bh[np * 2][0], bh[np * 2][1], bh[np * 2 + 1][0], bh[np * 2 + 1][1], bBaseH + bo);
                ldsm4(bl[np * 2][0], bl[np * 2][1], bl[np * 2 + 1][0], bl[np * 2 + 1][1], bBaseL + bo);
            }
#pragma unroll
            for (int mf = 0; mf < 4; mf++)
#pragma unroll
                for (int nf = 0; nf < 4; nf++) {
                    mma16816(acc[mf][nf], ah[mf], bh[nf]);
                    mma16816(acc[mf][nf], ah[mf], bl[nf]);
                    mma16816(acc[mf][nf], al[mf], bh[nf]);
                }
        }
    }

    // epilogue: c0,c1 -> (row = lane/4, col = 2*(lane%4)), c2,c3 -> row+8
#pragma unroll
    for (int mf = 0; mf < 4; mf++) {
#pragma unroll
        for (int nf = 0; nf < 4; nf++) {
            int row0 = rowBase + wr * 64 + mf * 16 + (lane >> 2);
            int col  = colBase + wc * 32 + nf * 8 + 2 * (lane & 3);
            float b0 = bias[col], b1 = bias[col + 1];
            if (row0 < M) {
                C[(size_t)row0 * N + col]     = acc[mf][nf][0] + b0;
                C[(size_t)row0 * N + col + 1] = acc[mf][nf][1] + b1;
            }
            int row1 = row0 + 8;
            if (row1 < M) {
                C[(size_t)row1 * N + col]     = acc[mf][nf][2] + b0;
                C[(size_t)row1 * N + col + 1] = acc[mf][nf][3] + b1;
            }
        }
    }
}

// ---------------- flash attention (fp32 SIMT) ----------------
#define ATT_STRIDE 68
#define ATT_SMEM_BYTES ((4 * 64 * ATT_STRIDE + 3 * 64) * 4)
__global__ void __launch_bounds__(256) attn_kernel(
    const float* __restrict__ q, const float* __restrict__ kv, float* __restrict__ o)
{
    extern __shared__ float sm[];
    float (*Qs)[ATT_STRIDE] = (float(*)[ATT_STRIDE])(sm);
    float (*Ks)[ATT_STRIDE] = (float(*)[ATT_STRIDE])(sm + 64 * ATT_STRIDE);
    float (*Vs)[ATT_STRIDE] = (float(*)[ATT_STRIDE])(sm + 2 * 64 * ATT_STRIDE);
    float (*Ps)[ATT_STRIDE] = (float(*)[ATT_STRIDE])(sm + 3 * 64 * ATT_STRIDE);
    float* rowM = sm + 4 * 64 * ATT_STRIDE;
    float* rowL = rowM + 64;
    float* rowC = rowL + 64;

    int tid = threadIdx.x, tx = tid & 15, ty = tid >> 4;
    int bh = blockIdx.y, b = bh >> 3, h = bh & 7;
    int qbase = blockIdx.x * 64;
    size_t qoff   = ((size_t)b * NTOK + qbase) * CDIM + h * HD;
    size_t kvbase = (size_t)b * NSR * 1024 + h * HD;

#pragma unroll
    for (int l = 0; l < 4; l++) {
        int idx = tid + l * 256;
        int i = idx >> 4, d4 = (idx & 15) << 2;
        *(float4*)&Qs[i][d4] = *(const float4*)&q[qoff + (size_t)i * CDIM + d4];
    }
    if (tid < 64) { rowM[tid] = -FLT_MAX; rowL[tid] = 0.f; }

    float acc[4][4];
#pragma unroll
    for (int i = 0; i < 4; i++)
#pragma unroll
        for (int j = 0; j < 4; j++) acc[i][j] = 0.f;

    for (int kb = 0; kb < NSR; kb += 64) {
        __syncthreads();
#pragma unroll
        for (int l = 0; l < 4; l++) {
            int idx = tid + l * 256;
            int m = idx >> 4, d4 = (idx & 15) << 2;
            int gm = kb + m;
            float4 kf = make_float4(0.f, 0.f, 0.f, 0.f);
            float4 vf = make_float4(0.f, 0.f, 0.f, 0.f);
            if (gm < NSR) {
                kf = *(const float4*)&kv[kvbase + (size_t)gm * 1024 + d4];
                vf = *(const float4*)&kv[kvbase + (size_t)gm * 1024 + 512 + d4];
            }
            *(float4*)&Ks[m][d4] = kf;
            *(float4*)&Vs[m][d4] = vf;
        }
        __syncthreads();

        float s4[4][4];
#pragma unroll
        for (int i = 0; i < 4; i++)
#pragma unroll
            for (int j = 0; j < 4; j++) s4[i][j] = 0.f;
#pragma unroll
        for (int k4 = 0; k4 < 64; k4 += 4) {
            float4 qf[4], kf[4];
#pragma unroll
            for (int i = 0; i < 4; i++) qf[i] = *(float4*)&Qs[ty * 4 + i][k4];
#pragma unroll
            for (int j = 0; j < 4; j++) kf[j] = *(float4*)&Ks[tx * 4 + j][k4];
#pragma unroll
            for (int i = 0; i < 4; i++)
#pragma unroll
                for (int j = 0; j < 4; j++)
                    s4[i][j] += qf[i].x * kf[j].x + qf[i].y * kf[j].y +
                                qf[i].z * kf[j].z + qf[i].w * kf[j].w;
        }
#pragma unroll
        for (int i = 0; i < 4; i++)
#pragma unroll
            for (int j = 0; j < 4; j++)
                Ps[ty * 4 + i][tx * 4 + j] = s4[i][j] * 0.125f;
        __syncthreads();

        if (tid < 64) {
            int valid = NSR - kb; if (valid > 64) valid = 64;
            float mOld = rowM[tid], tm = -FLT_MAX;
            for (int j = 0; j < valid; j++) tm = fmaxf(tm, Ps[tid][j]);
            float nm = fmaxf(mOld, tm);
            float corr = __expf(mOld - nm);
            float ssum = 0.f;
            for (int j = 0; j < 64; j++) {
                float p = (j < valid) ? __expf(Ps[tid][j] - nm) : 0.f;
                Ps[tid][j] = p; ssum += p;
            }
            rowL[tid] = rowL[tid] * corr + ssum;
            rowM[tid] = nm; rowC[tid] = corr;
        }
        __syncthreads();

#pragma unroll
        for (int i = 0; i < 4; i++) {
            float cr = rowC[ty * 4 + i];
#pragma unroll
            for (int j = 0; j < 4; j++) acc[i][j] *= cr;
        }
#pragma unroll
        for (int m4 = 0; m4 < 64; m4 += 4) {
            float pfa[4][4], vfa[4][4];
#pragma unroll
            for (int i = 0; i < 4; i++) {
                float4 p4 = *(float4*)&Ps[ty * 4 + i][m4];
                pfa[i][0] = p4.x; pfa[i][1] = p4.y; pfa[i][2] = p4.z; pfa[i][3] = p4.w;
            }
#pragma unroll
            for (int u = 0; u < 4; u++) {
                float4 v4 = *(float4*)&Vs[m4 + u][tx * 4];
                vfa[u][0] = v4.x; vfa[u][1] = v4.y; vfa[u][2] = v4.z; vfa[u][3] = v4.w;
            }
#pragma unroll
            for (int i = 0; i < 4; i++)
#pragma unroll
                for (int u = 0; u < 4; u++)
#pragma unroll
                    for (int j = 0; j < 4; j++)
                        acc[i][j] += pfa[i][u] * vfa[u][j];
        }
    }
#pragma unroll
    for (int i = 0; i < 4; i++) {
        int r = ty * 4 + i;
        float invl = 1.f / rowL[r];
#pragma unroll
        for (int j = 0; j < 4; j++)
            o[((size_t)b * NTOK + qbase + r) * CDIM + h * HD + tx * 4 + j] = acc[i][j] * invl;
    }
}

// ---------------- trilinear upsample of V + LN + add o -> bf16 hi/lo ----------------
__global__ void __launch_bounds__(256) ups_ln_add_kernel(
    const float* __restrict__ kv, const float* __restrict__ ob,
    const float* __restrict__ g, const float* __restrict__ beta,
    __nv_bfloat16* __restrict__ yh, __nv_bfloat16* __restrict__ yl)
{
    int bn = blockIdx.x;
    int b = bn / NTOK, n = bn % NTOK;
    int d = n / 400, hh = (n / 20) % 20, ww = n % 20;
    float sd = d  * 0.5f - 0.25f; int fd = (int)floorf(sd); float wdz = sd - (float)fd;
    float sh = hh * 0.5f - 0.25f; int fh = (int)floorf(sh); float why = sh - (float)fh;
    float sw = ww * 0.5f - 0.25f; int fw = (int)floorf(sw); float wwx = sw - (float)fw;
    int dz0 = fd < 0 ? 0 : fd; int dz1 = (fd + 1) > 9 ? 9 : (fd + 1);
    int hy0 = fh < 0 ? 0 : fh; int hy1 = (fh + 1) > 9 ? 9 : (fh + 1);
    int wx0 = fw < 0 ? 0 : fw; int wx1 = (fw + 1) > 9 ? 9 : (fw + 1);
    int midx[8]; float wt8[8];
    {
        int zz[2] = {dz0, dz1};  float wz[2] = {1.f - wdz, wdz};
        int yy[2] = {hy0, hy1};  float wy[2] = {1.f - why, why};
        int xx[2] = {wx0, wx1};  float wx[2] = {1.f - wwx, wwx};
        int t = 0;
        for (int a = 0; a < 2; a++)
            for (int b2 = 0; b2 < 2; b2++)
                for (int c2 = 0; c2 < 2; c2++) {
                    midx[t] = zz[a] * 100 + yy[b2] * 10 + xx[c2];
                    wt8[t]  = wz[a] * wy[b2] * wx[c2]; t++;
                }
    }
    __shared__ float vals[CDIM];
    __shared__ float red[18];
    size_t kvb = (size_t)b * NSR * 1024 + 512;
    float loc[2];
#pragma unroll
    for (int ci = 0; ci < 2; ci++) {
        int c = threadIdx.x + ci * 256;
        float acc = 0.f;
#pragma unroll
        for (int t = 0; t < 8; t++)
            acc += wt8[t] * kv[kvb + (size_t)midx[t] * 1024 + c];
        vals[c] = acc; loc[ci] = acc;
    }
    float s = loc[0] + loc[1], sq = loc[0] * loc[0] + loc[1] * loc[1];
#pragma unroll
    for (int o2 = 16; o2 > 0; o2 >>= 1) {
        s  += __shfl_down_sync(0xffffffffu, s,  o2);
        sq += __shfl_down_sync(0xffffffffu, sq, o2);
    }
    int w = threadIdx.x >> 5;
    if ((threadIdx.x & 31) == 0) { red[w] = s; red[8 + w] = sq; }
    __syncthreads();
    if (threadIdx.x == 0) {
        float a = 0.f, b2 = 0.f;
        for (int i = 0; i < 8; i++) { a += red[i]; b2 += red[8 + i]; }
        red[16] = a; red[17] = b2;
    }
    __syncthreads();
    float mean = red[16] * (1.f / CDIM);
    float var  = red[17] * (1.f / CDIM) - mean * mean;
    float inv  = rsqrtf(var + 1e-6f);
#pragma unroll
    for (int ci = 0; ci < 2; ci++) {
        int c = threadIdx.x + ci * 256;
        size_t oidx = ((size_t)b * NTOK + n) * CDIM + c;
        float v = ob[oidx] + (vals[c] - mean) * inv * g[c] + beta[c];
        __nv_bfloat16 hb = __float2bfloat16(v);
        yh[oidx] = hb;
        yl[oidx] = __float2bfloat16(v - __bfloat162float(hb));
    }
}

// ---------------- launch ----------------
extern "C" void kernel_launch(void* const* d_in, const int* in_sizes, int n_in,
                              void* d_out, int out_size)
{
    const float* x      = (const float*)d_in[0];
    const float* Wq     = (const float*)d_in[1];
    const float* bq     = (const float*)d_in[2];
    const float* Wkv    = (const float*)d_in[3];
    const float* bkv    = (const float*)d_in[4];
    const float* srw    = (const float*)d_in[5];
    const float* srb    = (const float*)d_in[6];
    const float* srg    = (const float*)d_in[7];
    const float* srbeta = (const float*)d_in[8];
    const float* upg    = (const float*)d_in[9];
    const float* upbeta = (const float*)d_in[10];
    const float* Wp     = (const float*)d_in[11];
    const float* bp     = (const float*)d_in[12];
    float* out = (float*)d_out;

    float *kvb, *qb, *ob;
    __nv_bfloat16 *xh, *xl, *yh, *yl, *xrh, *xrl, *wqh, *wql, *wkvh, *wkvl, *wph, *wpl;
    cudaGetSymbolAddress((void**)&kvb, g_kv);
    cudaGetSymbolAddress((void**)&qb,  g_q);
    cudaGetSymbolAddress((void**)&ob,  g_o);
    cudaGetSymbolAddress((void**)&xh,  g_xh);
    cudaGetSymbolAddress((void**)&xl,  g_xl);
    cudaGetSymbolAddress((void**)&yh,  g_yh);
    cudaGetSymbolAddress((void**)&yl,  g_yl);
    cudaGetSymbolAddress((void**)&xrh, g_xrh);
    cudaGetSymbolAddress((void**)&xrl, g_xrl);
    cudaGetSymbolAddress((void**)&wqh, g_wqt_h);
    cudaGetSymbolAddress((void**)&wql, g_wqt_l);
    cudaGetSymbolAddress((void**)&wkvh, g_wkvt_h);
    cudaGetSymbolAddress((void**)&wkvl, g_wkvt_l);
    cudaGetSymbolAddress((void**)&wph, g_wpt_h);
    cudaGetSymbolAddress((void**)&wpl, g_wpt_l);

    cudaFuncSetAttribute(attn_kernel, cudaFuncAttributeMaxDynamicSharedMemorySize, ATT_SMEM_BYTES);

    int nx = BATCH * NTOK * CDIM;
    split_kernel<<<(nx + 255) / 256, 256>>>(x, xh, xl, nx);
    wsplit_t_kernel<<<dim3(512 / 32, 512 / 32), 256>>>(Wq, wqh, wql, 512, 512);
    wsplit_t_kernel<<<dim3(1024 / 32, 512 / 32), 256>>>(Wkv, wkvh, wkvl, 512, 1024);
    wsplit_t_kernel<<<dim3(512 / 32, 512 / 32), 256>>>(Wp, wph, wpl, 512, 512);

    conv_ln_kernel<<<BATCH * NSR, 256>>>(x, srw, srb, srg, srbeta, xrh, xrl);

    // kv = xr @ Wkv + bkv  (2000 x 1024)
    gemm_mma_kernel<<<dim3(1024 / 128, (BATCH * NSR + 127) / 128), 256>>>(
        xrh, xrl, wkvh, wkvl, bkv, kvb, BATCH * NSR, 1024);
    // q = x @ Wq + bq  (16000 x 512)
    gemm_mma_kernel<<<dim3(512 / 128, (BATCH * NTOK) / 128), 256>>>(
        xh, xl, wqh, wql, bq, qb, BATCH * NTOK, 512);

    attn_kernel<<<dim3(NTOK / 64, BATCH * NHEADS), 256, ATT_SMEM_BYTES>>>(qb, kvb, ob);

    ups_ln_add_kernel<<<BATCH * NTOK, 256>>>(kvb, ob, upg, upbeta, yh, yl);

    // out = y @ Wp + bp  (16000 x 512)
    gemm_mma_kernel<<<dim3(512 / 128, (BATCH * NTOK) / 128), 256>>>(
        yh, yl, wph, wpl, bp, out, BATCH * NTOK, 512);
}

// round 5
// speedup vs baseline: 3.3359x; 2.9311x over previous
#include <cuda_runtime.h>
#include <cuda_bf16.h>
#include <math.h>
#include <float.h>
#include <stdint.h>

#define BATCH 2
#define NTOK  8000
#define CDIM  512
#define NSR   1000
#define NHEADS 8
#define HD    64

__device__ float g_kv[BATCH * NSR * 2 * CDIM];
__device__ float g_o [BATCH * NTOK * CDIM];
__device__ __nv_bfloat16 g_xh [BATCH * NTOK * CDIM];
__device__ __nv_bfloat16 g_xl [BATCH * NTOK * CDIM];
__device__ __nv_bfloat16 g_yh [BATCH * NTOK * CDIM];
__device__ __nv_bfloat16 g_yl [BATCH * NTOK * CDIM];
__device__ __nv_bfloat16 g_qh [BATCH * NTOK * CDIM];
__device__ __nv_bfloat16 g_ql [BATCH * NTOK * CDIM];
__device__ __nv_bfloat16 g_kvh[BATCH * NSR * 2 * CDIM];
__device__ __nv_bfloat16 g_kvl[BATCH * NSR * 2 * CDIM];
__device__ __nv_bfloat16 g_xrh[BATCH * NSR * CDIM];
__device__ __nv_bfloat16 g_xrl[BATCH * NSR * CDIM];
__device__ __nv_bfloat16 g_wqt_h [CDIM * CDIM];
__device__ __nv_bfloat16 g_wqt_l [CDIM * CDIM];
__device__ __nv_bfloat16 g_wkvt_h[2 * CDIM * CDIM];
__device__ __nv_bfloat16 g_wkvt_l[2 * CDIM * CDIM];
__device__ __nv_bfloat16 g_wpt_h [CDIM * CDIM];
__device__ __nv_bfloat16 g_wpt_l [CDIM * CDIM];

// ---------------- mma.sync helpers ----------------
__device__ __forceinline__ void ldsm4(uint32_t& r0, uint32_t& r1, uint32_t& r2, uint32_t& r3,
                                      uint32_t addr)
{
    asm volatile("ldmatrix.sync.aligned.m8n8.x4.shared.b16 {%0,%1,%2,%3}, [%4];"
                 : "=r"(r0), "=r"(r1), "=r"(r2), "=r"(r3) : "r"(addr));
}
__device__ __forceinline__ void ldsm4t(uint32_t& r0, uint32_t& r1, uint32_t& r2, uint32_t& r3,
                                       uint32_t addr)
{
    asm volatile("ldmatrix.sync.aligned.m8n8.x4.trans.shared.b16 {%0,%1,%2,%3}, [%4];"
                 : "=r"(r0), "=r"(r1), "=r"(r2), "=r"(r3) : "r"(addr));
}
__device__ __forceinline__ void mma16816(float* c, const uint32_t* a, const uint32_t* b)
{
    asm volatile("mma.sync.aligned.m16n8k16.row.col.f32.bf16.bf16.f32 "
                 "{%0,%1,%2,%3}, {%4,%5,%6,%7}, {%8,%9}, {%0,%1,%2,%3};"
                 : "+f"(c[0]), "+f"(c[1]), "+f"(c[2]), "+f"(c[3])
                 : "r"(a[0]), "r"(a[1]), "r"(a[2]), "r"(a[3]), "r"(b[0]), "r"(b[1]));
}

// ---------------- split fp32 -> bf16 hi/lo ----------------
__global__ void __launch_bounds__(256) split_kernel(
    const float* __restrict__ s, __nv_bfloat16* __restrict__ h,
    __nv_bfloat16* __restrict__ l, int n)
{
    int i = blockIdx.x * 256 + threadIdx.x;
    if (i < n) {
        float v = s[i];
        __nv_bfloat16 hh = __float2bfloat16(v);
        h[i] = hh;
        l[i] = __float2bfloat16(v - __bfloat162float(hh));
    }
}

// ---------------- transpose + split W[K][N] -> T[N][K] bf16 hi/lo ----------------
__global__ void __launch_bounds__(256) wsplit_t_kernel(
    const float* __restrict__ W, __nv_bfloat16* __restrict__ Th,
    __nv_bfloat16* __restrict__ Tl, int K, int N)
{
    __shared__ float t[32][33];
    int tx = threadIdx.x & 31, ty = threadIdx.x >> 5;
    int nb = blockIdx.x * 32, kb = blockIdx.y * 32;
#pragma unroll
    for (int i = ty; i < 32; i += 8)
        t[i][tx] = W[(size_t)(kb + i) * N + nb + tx];
    __syncthreads();
#pragma unroll
    for (int i = ty; i < 32; i += 8) {
        float v = t[tx][i];
        __nv_bfloat16 hh = __float2bfloat16(v);
        Th[(size_t)(nb + i) * K + kb + tx] = hh;
        Tl[(size_t)(nb + i) * K + kb + tx] = __float2bfloat16(v - __bfloat162float(hh));
    }
}

// ---------------- conv3d depthwise (3,s2,p1) + bias + LN -> bf16 hi/lo ----------------
__global__ void __launch_bounds__(256) conv_ln_kernel(
    const float* __restrict__ x, const float* __restrict__ srw,
    const float* __restrict__ srb, const float* __restrict__ g,
    const float* __restrict__ beta,
    __nv_bfloat16* __restrict__ xrh, __nv_bfloat16* __restrict__ xrl)
{
    int bp = blockIdx.x;
    int b = bp / NSR, opos = bp % NSR;
    int od = opos / 100, oh = (opos / 10) % 10, ow = opos % 10;
    __shared__ float vals[CDIM];
    __shared__ float red[18];
    float loc[2];
#pragma unroll
    for (int ci = 0; ci < 2; ci++) {
        int c = threadIdx.x + ci * 256;
        float acc = srb[c];
#pragma unroll
        for (int kd = 0; kd < 3; kd++) {
            int id = od * 2 - 1 + kd;
            if ((unsigned)id >= 20u) continue;
#pragma unroll
            for (int kh = 0; kh < 3; kh++) {
                int ih = oh * 2 - 1 + kh;
                if ((unsigned)ih >= 20u) continue;
#pragma unroll
                for (int kw = 0; kw < 3; kw++) {
                    int iw = ow * 2 - 1 + kw;
                    if ((unsigned)iw >= 20u) continue;
                    acc += x[((size_t)b * NTOK + id * 400 + ih * 20 + iw) * CDIM + c] *
                           srw[c * 27 + kd * 9 + kh * 3 + kw];
                }
            }
        }
        vals[c] = acc; loc[ci] = acc;
    }
    float s = loc[0] + loc[1], sq = loc[0] * loc[0] + loc[1] * loc[1];
#pragma unroll
    for (int o2 = 16; o2 > 0; o2 >>= 1) {
        s  += __shfl_down_sync(0xffffffffu, s,  o2);
        sq += __shfl_down_sync(0xffffffffu, sq, o2);
    }
    int w = threadIdx.x >> 5;
    if ((threadIdx.x & 31) == 0) { red[w] = s; red[8 + w] = sq; }
    __syncthreads();
    if (threadIdx.x == 0) {
        float a = 0.f, b2 = 0.f;
        for (int i = 0; i < 8; i++) { a += red[i]; b2 += red[8 + i]; }
        red[16] = a; red[17] = b2;
    }
    __syncthreads();
    float mean = red[16] * (1.f / CDIM);
    float var  = red[17] * (1.f / CDIM) - mean * mean;
    float inv  = rsqrtf(var + 1e-6f);
#pragma unroll
    for (int ci = 0; ci < 2; ci++) {
        int c = threadIdx.x + ci * 256;
        float v = (vals[c] - mean) * inv * g[c] + beta[c];
        size_t idx = ((size_t)b * NSR + opos) * CDIM + c;
        __nv_bfloat16 hh = __float2bfloat16(v);
        xrh[idx] = hh;
        xrl[idx] = __float2bfloat16(v - __bfloat162float(hh));
    }
}

// ---------------- tensor-core GEMM: C = (Ah+Al)[M,512] @ (Bh+Bl)[N,512]^T + bias ----------------
// Optional outputs: f32 C, and/or bf16 hi/lo (Ch, Cl).
#define SMS 40
__global__ void __launch_bounds__(256) gemm_mma_kernel(
    const __nv_bfloat16* __restrict__ Ah, const __nv_bfloat16* __restrict__ Al,
    const __nv_bfloat16* __restrict__ Bh, const __nv_bfloat16* __restrict__ Bl,
    const float* __restrict__ bias, float* __restrict__ C,
    __nv_bfloat16* __restrict__ Ch, __nv_bfloat16* __restrict__ Cl, int M, int N)
{
    __shared__ __nv_bfloat16 sAh[128 * SMS], sAl[128 * SMS], sBh[128 * SMS], sBl[128 * SMS];

    int tid = threadIdx.x, wid = tid >> 5, lane = tid & 31;
    int wr = wid >> 2, wc = wid & 3;
    int rowBase = blockIdx.y * 128, colBase = blockIdx.x * 128;

    float acc[4][4][4];
#pragma unroll
    for (int i = 0; i < 4; i++)
#pragma unroll
        for (int j = 0; j < 4; j++)
#pragma unroll
            for (int k = 0; k < 4; k++) acc[i][j][k] = 0.f;

    uint32_t aBaseH = (uint32_t)__cvta_generic_to_shared(sAh);
    uint32_t aBaseL = (uint32_t)__cvta_generic_to_shared(sAl);
    uint32_t bBaseH = (uint32_t)__cvta_generic_to_shared(sBh);
    uint32_t bBaseL = (uint32_t)__cvta_generic_to_shared(sBl);

    for (int k0 = 0; k0 < 512; k0 += 32) {
        __syncthreads();
#pragma unroll
        for (int it = 0; it < 2; it++) {
            int idx = tid + it * 256;
            int r = idx >> 2, c = idx & 3;
            int ar = rowBase + r; if (ar > M - 1) ar = M - 1;
            int br = colBase + r;
            size_t aoff = (size_t)ar * 512 + k0 + c * 8;
            size_t boff = (size_t)br * 512 + k0 + c * 8;
            int soff = r * SMS + c * 8;
            *(uint4*)&sAh[soff] = *(const uint4*)&Ah[aoff];
            *(uint4*)&sAl[soff] = *(const uint4*)&Al[aoff];
            *(uint4*)&sBh[soff] = *(const uint4*)&Bh[boff];
            *(uint4*)&sBl[soff] = *(const uint4*)&Bl[boff];
        }
        __syncthreads();

#pragma unroll
        for (int ks = 0; ks < 32; ks += 16) {
            uint32_t aoffs = (uint32_t)(((wr * 64 + (lane & 15)) * SMS + ks + ((lane >> 4) << 3)) * 2);
            uint32_t boffs = (uint32_t)(((wc * 32 + ((lane >> 4) << 3) + (lane & 7)) * SMS + ks + (((lane >> 3) & 1) << 3)) * 2);

            uint32_t ah[4][4], al[4][4];
#pragma unroll
            for (int mf = 0; mf < 4; mf++) {
                uint32_t ao = aoffs + (uint32_t)(mf * 16 * SMS * 2);
                ldsm4(ah[mf][0], ah[mf][1], ah[mf][2], ah[mf][3], aBaseH + ao);
                ldsm4(al[mf][0], al[mf][1], al[mf][2], al[mf][3], aBaseL + ao);
            }
            uint32_t bh[4][2], bl[4][2];
#pragma unroll
            for (int np = 0; np < 2; np++) {
                uint32_t bo = boffs + (uint32_t)(np * 16 * SMS * 2);
                ldsm4(bh[np * 2][0], bh[np * 2][1], bh[np * 2 + 1][0], bh[np * 2 + 1][1], bBaseH + bo);
                ldsm4(bl[np * 2][0], bl[np * 2][1], bl[np * 2 + 1][0], bl[np * 2 + 1][1], bBaseL + bo);
            }
#pragma unroll
            for (int mf = 0; mf < 4; mf++)
#pragma unroll
                for (int nf = 0; nf < 4; nf++) {
                    mma16816(acc[mf][nf], ah[mf], bh[nf]);
                    mma16816(acc[mf][nf], ah[mf], bl[nf]);
                    mma16816(acc[mf][nf], al[mf], bh[nf]);
                }
        }
    }

#pragma unroll
    for (int mf = 0; mf < 4; mf++) {
#pragma unroll
        for (int nf = 0; nf < 4; nf++) {
            int row0 = rowBase + wr * 64 + mf * 16 + (lane >> 2);
            int col  = colBase + wc * 32 + nf * 8 + 2 * (lane & 3);
            float b0 = bias[col], b1 = bias[col + 1];
#pragma unroll
            for (int half = 0; half < 2; half++) {
                int row = row0 + half * 8;
                if (row < M) {
                    float v0 = acc[mf][nf][half * 2]     + b0;
                    float v1 = acc[mf][nf][half * 2 + 1] + b1;
                    size_t o0 = (size_t)row * N + col;
                    if (C) { C[o0] = v0; C[o0 + 1] = v1; }
                    if (Ch) {
                        __nv_bfloat16 h0 = __float2bfloat16(v0);
                        __nv_bfloat16 h1 = __float2bfloat16(v1);
                        Ch[o0] = h0; Ch[o0 + 1] = h1;
                        Cl[o0]     = __float2bfloat16(v0 - __bfloat162float(h0));
                        Cl[o0 + 1] = __float2bfloat16(v1 - __bfloat162float(h1));
                    }
                }
            }
        }
    }
}

// ---------------- flash attention on tensor cores (bf16 split, fp32 softmax) ----------------
#define AST 72
#define ATT2_SMEM (6 * 64 * AST * 2)
__global__ void __launch_bounds__(128) attn_mma_kernel(
    const __nv_bfloat16* __restrict__ qh, const __nv_bfloat16* __restrict__ ql,
    const __nv_bfloat16* __restrict__ kvh, const __nv_bfloat16* __restrict__ kvl,
    float* __restrict__ o)
{
    extern __shared__ __nv_bfloat16 asmem[];
    __nv_bfloat16* sQh = asmem;
    __nv_bfloat16* sQl = asmem + 64 * AST;
    __nv_bfloat16* sKh = asmem + 2 * 64 * AST;
    __nv_bfloat16* sKl = asmem + 3 * 64 * AST;
    __nv_bfloat16* sVh = asmem + 4 * 64 * AST;
    __nv_bfloat16* sVl = asmem + 5 * 64 * AST;

    int tid = threadIdx.x, wid = tid >> 5, lane = tid & 31;
    int bh = blockIdx.y, b = bh >> 3, h = bh & 7;
    int qbase = blockIdx.x * 64;
    size_t qoff = ((size_t)b * NTOK + qbase) * CDIM + h * HD;

#pragma unroll
    for (int i = 0; i < 4; i++) {
        int idx = tid + i * 128;
        int r = idx >> 3, c = (idx & 7) << 3;
        *(uint4*)&sQh[r * AST + c] = *(const uint4*)&qh[qoff + (size_t)r * CDIM + c];
        *(uint4*)&sQl[r * AST + c] = *(const uint4*)&ql[qoff + (size_t)r * CDIM + c];
    }
    __syncthreads();

    uint32_t bQh = (uint32_t)__cvta_generic_to_shared(sQh);
    uint32_t bQl = (uint32_t)__cvta_generic_to_shared(sQl);
    uint32_t bKh = (uint32_t)__cvta_generic_to_shared(sKh);
    uint32_t bKl = (uint32_t)__cvta_generic_to_shared(sKl);
    uint32_t bVh = (uint32_t)__cvta_generic_to_shared(sVh);
    uint32_t bVl = (uint32_t)__cvta_generic_to_shared(sVl);

    uint32_t qfh[4][4], qfl[4][4];
    {
        uint32_t qrow = (uint32_t)(wid * 16 + (lane & 15));
#pragma unroll
        for (int kt = 0; kt < 4; kt++) {
            uint32_t off = (qrow * AST + kt * 16 + ((lane >> 4) << 3)) * 2;
            ldsm4(qfh[kt][0], qfh[kt][1], qfh[kt][2], qfh[kt][3], bQh + off);
            ldsm4(qfl[kt][0], qfl[kt][1], qfl[kt][2], qfl[kt][3], bQl + off);
        }
    }

    float acc[8][4];
#pragma unroll
    for (int i = 0; i < 8; i++)
#pragma unroll
        for (int j = 0; j < 4; j++) acc[i][j] = 0.f;
    float m0 = -FLT_MAX, m1 = -FLT_MAX, l0 = 0.f, l1 = 0.f;

    size_t kvoff = (size_t)b * NSR * 1024 + h * HD;
    int cbase = 2 * (lane & 3);

    for (int kb = 0; kb < NSR; kb += 64) {
        __syncthreads();
#pragma unroll
        for (int i = 0; i < 4; i++) {
            int idx = tid + i * 128;
            int r = idx >> 3, c = (idx & 7) << 3;
            int gm = kb + r;
            uint4 z = make_uint4(0u, 0u, 0u, 0u);
            uint4 a0 = z, a1 = z, a2 = z, a3 = z;
            if (gm < NSR) {
                size_t base = kvoff + (size_t)gm * 1024 + c;
                a0 = *(const uint4*)&kvh[base];
                a1 = *(const uint4*)&kvl[base];
                a2 = *(const uint4*)&kvh[base + 512];
                a3 = *(const uint4*)&kvl[base + 512];
            }
            *(uint4*)&sKh[r * AST + c] = a0;
            *(uint4*)&sKl[r * AST + c] = a1;
            *(uint4*)&sVh[r * AST + c] = a2;
            *(uint4*)&sVl[r * AST + c] = a3;
        }
        __syncthreads();

        // S = Q K^T (3-term split)
        float s_[8][4];
#pragma unroll
        for (int i = 0; i < 8; i++)
#pragma unroll
            for (int j = 0; j < 4; j++) s_[i][j] = 0.f;

#pragma unroll
        for (int kt = 0; kt < 4; kt++) {
#pragma unroll
            for (int np = 0; np < 4; np++) {
                uint32_t brow = (uint32_t)(np * 16 + ((lane >> 4) << 3) + (lane & 7));
                uint32_t boff = (brow * AST + kt * 16 + (((lane >> 3) & 1) << 3)) * 2;
                uint32_t h0, h1, h2, h3, g0, g1, g2, g3;
                ldsm4(h0, h1, h2, h3, bKh + boff);
                ldsm4(g0, g1, g2, g3, bKl + boff);
                uint32_t fh0[2] = {h0, h1}, fh1[2] = {h2, h3};
                uint32_t fl0[2] = {g0, g1}, fl1[2] = {g2, g3};
                mma16816(s_[np * 2],     qfh[kt], fh0);
                mma16816(s_[np * 2],     qfh[kt], fl0);
                mma16816(s_[np * 2],     qfl[kt], fh0);
                mma16816(s_[np * 2 + 1], qfh[kt], fh1);
                mma16816(s_[np * 2 + 1], qfh[kt], fl1);
                mma16816(s_[np * 2 + 1], qfl[kt], fh1);
            }
        }

        // online softmax (register, quad shuffles)
        int valid = NSR - kb; if (valid > 64) valid = 64;
        float rm0 = -FLT_MAX, rm1 = -FLT_MAX;
#pragma unroll
        for (int nt = 0; nt < 8; nt++) {
#pragma unroll
            for (int j = 0; j < 4; j++) s_[nt][j] *= 0.125f;
            rm0 = fmaxf(rm0, fmaxf(s_[nt][0], s_[nt][1]));
            rm1 = fmaxf(rm1, fmaxf(s_[nt][2], s_[nt][3]));
        }
        rm0 = fmaxf(rm0, __shfl_xor_sync(0xffffffffu, rm0, 1));
        rm0 = fmaxf(rm0, __shfl_xor_sync(0xffffffffu, rm0, 2));
        rm1 = fmaxf(rm1, __shfl_xor_sync(0xffffffffu, rm1, 1));
        rm1 = fmaxf(rm1, __shfl_xor_sync(0xffffffffu, rm1, 2));
        float nm0 = fmaxf(m0, rm0), nm1 = fmaxf(m1, rm1);
        float corr0 = __expf(m0 - nm0), corr1 = __expf(m1 - nm1);
        m0 = nm0; m1 = nm1;

        float sum0 = 0.f, sum1 = 0.f;
#pragma unroll
        for (int nt = 0; nt < 8; nt++) {
            int c0 = nt * 8 + cbase;
            float p0 = (c0     < valid) ? __expf(s_[nt][0] - nm0) : 0.f;
            float p1 = (c0 + 1 < valid) ? __expf(s_[nt][1] - nm0) : 0.f;
            float p2 = (c0     < valid) ? __expf(s_[nt][2] - nm1) : 0.f;
            float p3 = (c0 + 1 < valid) ? __expf(s_[nt][3] - nm1) : 0.f;
            sum0 += p0 + p1; sum1 += p2 + p3;
            s_[nt][0] = p0; s_[nt][1] = p1; s_[nt][2] = p2; s_[nt][3] = p3;
        }
        sum0 += __shfl_xor_sync(0xffffffffu, sum0, 1);
        sum0 += __shfl_xor_sync(0xffffffffu, sum0, 2);
        sum1 += __shfl_xor_sync(0xffffffffu, sum1, 1);
        sum1 += __shfl_xor_sync(0xffffffffu, sum1, 2);
        l0 = l0 * corr0 + sum0;
        l1 = l1 * corr1 + sum1;

#pragma unroll
        for (int nt = 0; nt < 8; nt++) {
            acc[nt][0] *= corr0; acc[nt][1] *= corr0;
            acc[nt][2] *= corr1; acc[nt][3] *= corr1;
        }

        // O += P V (3-term split), P repacked from S C-frags
#pragma unroll
        for (int kt = 0; kt < 4; kt++) {
            uint32_t ph[4], pl[4];
#pragma unroll
            for (int q2 = 0; q2 < 2; q2++) {
                int nt = 2 * kt + q2;
                __nv_bfloat162 hA = __floats2bfloat162_rn(s_[nt][0], s_[nt][1]);
                __nv_bfloat162 hB = __floats2bfloat162_rn(s_[nt][2], s_[nt][3]);
                __nv_bfloat162 lA = __floats2bfloat162_rn(
                    s_[nt][0] - __low2float(hA), s_[nt][1] - __high2float(hA));
                __nv_bfloat162 lB = __floats2bfloat162_rn(
                    s_[nt][2] - __low2float(hB), s_[nt][3] - __high2float(hB));
                ph[q2 * 2]     = *(uint32_t*)&hA;
                ph[q2 * 2 + 1] = *(uint32_t*)&hB;
                pl[q2 * 2]     = *(uint32_t*)&lA;
                pl[q2 * 2 + 1] = *(uint32_t*)&lB;
            }
            int l8 = lane >> 3, li = lane & 7;
#pragma unroll
            for (int np = 0; np < 4; np++) {
                uint32_t vrow = (uint32_t)(kt * 16 + ((l8 & 1) << 3) + li);
                uint32_t vcol = (uint32_t)(np * 16 + ((l8 >> 1) << 3));
                uint32_t voff = (vrow * AST + vcol) * 2;
                uint32_t h0, h1, h2, h3, g0, g1, g2, g3;
                ldsm4t(h0, h1, h2, h3, bVh + voff);
                ldsm4t(g0, g1, g2, g3, bVl + voff);
                uint32_t fh0[2] = {h0, h1}, fh1[2] = {h2, h3};
                uint32_t fl0[2] = {g0, g1}, fl1[2] = {g2, g3};
                mma16816(acc[np * 2],     ph, fh0);
                mma16816(acc[np * 2],     ph, fl0);
                mma16816(acc[np * 2],     pl, fh0);
                mma16816(acc[np * 2 + 1], ph, fh1);
                mma16816(acc[np * 2 + 1], ph, fl1);
                mma16816(acc[np * 2 + 1], pl, fh1);
            }
        }
    }

    float inv0 = 1.f / l0, inv1 = 1.f / l1;
    int r0 = qbase + wid * 16 + (lane >> 2);
    size_t ob0 = ((size_t)b * NTOK + r0) * CDIM + h * HD;
    size_t ob1 = ob0 + (size_t)8 * CDIM;
#pragma unroll
    for (int nt = 0; nt < 8; nt++) {
        int cc = nt * 8 + cbase;
        o[ob0 + cc]     = acc[nt][0] * inv0;
        o[ob0 + cc + 1] = acc[nt][1] * inv0;
        o[ob1 + cc]     = acc[nt][2] * inv1;
        o[ob1 + cc + 1] = acc[nt][3] * inv1;
    }
}

// ---------------- trilinear upsample of V + LN + add o -> bf16 hi/lo ----------------
__global__ void __launch_bounds__(256) ups_ln_add_kernel(
    const float* __restrict__ kv, const float* __restrict__ ob,
    const float* __restrict__ g, const float* __restrict__ beta,
    __nv_bfloat16* __restrict__ yh, __nv_bfloat16* __restrict__ yl)
{
    int bn = blockIdx.x;
    int b = bn / NTOK, n = bn % NTOK;
    int d = n / 400, hh = (n / 20) % 20, ww = n % 20;
    float sd = d  * 0.5f - 0.25f; int fd = (int)floorf(sd); float wdz = sd - (float)fd;
    float sh = hh * 0.5f - 0.25f; int fh = (int)floorf(sh); float why = sh - (float)fh;
    float sw = ww * 0.5f - 0.25f; int fw = (int)floorf(sw); float wwx = sw - (float)fw;
    int dz0 = fd < 0 ? 0 : fd; int dz1 = (fd + 1) > 9 ? 9 : (fd + 1);
    int hy0 = fh < 0 ? 0 : fh; int hy1 = (fh + 1) > 9 ? 9 : (fh + 1);
    int wx0 = fw < 0 ? 0 : fw; int wx1 = (fw + 1) > 9 ? 9 : (fw + 1);
    int midx[8]; float wt8[8];
    {
        int zz[2] = {dz0, dz1};  float wz[2] = {1.f - wdz, wdz};
        int yy[2] = {hy0, hy1};  float wy[2] = {1.f - why, why};
        int xx[2] = {wx0, wx1};  float wx[2] = {1.f - wwx, wwx};
        int t = 0;
        for (int a = 0; a < 2; a++)
            for (int b2 = 0; b2 < 2; b2++)
                for (int c2 = 0; c2 < 2; c2++) {
                    midx[t] = zz[a] * 100 + yy[b2] * 10 + xx[c2];
                    wt8[t]  = wz[a] * wy[b2] * wx[c2]; t++;
                }
    }
    __shared__ float vals[CDIM];
    __shared__ float red[18];
    size_t kvb = (size_t)b * NSR * 1024 + 512;
    float loc[2];
#pragma unroll
    for (int ci = 0; ci < 2; ci++) {
        int c = threadIdx.x + ci * 256;
        float acc = 0.f;
#pragma unroll
        for (int t = 0; t < 8; t++)
            acc += wt8[t] * kv[kvb + (size_t)midx[t] * 1024 + c];
        vals[c] = acc; loc[ci] = acc;
    }
    float s = loc[0] + loc[1], sq = loc[0] * loc[0] + loc[1] * loc[1];
#pragma unroll
    for (int o2 = 16; o2 > 0; o2 >>= 1) {
        s  += __shfl_down_sync(0xffffffffu, s,  o2);
        sq += __shfl_down_sync(0xffffffffu, sq, o2);
    }
    int w = threadIdx.x >> 5;
    if ((threadIdx.x & 31) == 0) { red[w] = s; red[8 + w] = sq; }
    __syncthreads();
    if (threadIdx.x == 0) {
        float a = 0.f, b2 = 0.f;
        for (int i = 0; i < 8; i++) { a += red[i]; b2 += red[8 + i]; }
        red[16] = a; red[17] = b2;
    }
    __syncthreads();
    float mean = red[16] * (1.f / CDIM);
    float var  = red[17] * (1.f / CDIM) - mean * mean;
    float inv  = rsqrtf(var + 1e-6f);
#pragma unroll
    for (int ci = 0; ci < 2; ci++) {
        int c = threadIdx.x + ci * 256;
        size_t oidx = ((size_t)b * NTOK + n) * CDIM + c;
        float v = ob[oidx] + (vals[c] - mean) * inv * g[c] + beta[c];
        __nv_bfloat16 hb = __float2bfloat16(v);
        yh[oidx] = hb;
        yl[oidx] = __float2bfloat16(v - __bfloat162float(hb));
    }
}

// ---------------- launch ----------------
extern "C" void kernel_launch(void* const* d_in, const int* in_sizes, int n_in,
                              void* d_out, int out_size)
{
    const float* x      = (const float*)d_in[0];
    const float* Wq     = (const float*)d_in[1];
    const float* bq     = (const float*)d_in[2];
    const float* Wkv    = (const float*)d_in[3];
    const float* bkv    = (const float*)d_in[4];
    const float* srw    = (const float*)d_in[5];
    const float* srb    = (const float*)d_in[6];
    const float* srg    = (const float*)d_in[7];
    const float* srbeta = (const float*)d_in[8];
    const float* upg    = (const float*)d_in[9];
    const float* upbeta = (const float*)d_in[10];
    const float* Wp     = (const float*)d_in[11];
    const float* bp     = (const float*)d_in[12];
    float* out = (float*)d_out;

    float *kvb, *ob;
    __nv_bfloat16 *xh, *xl, *yh, *yl, *xrh, *xrl, *qh, *ql, *kvh, *kvl;
    __nv_bfloat16 *wqh, *wql, *wkvh, *wkvl, *wph, *wpl;
    cudaGetSymbolAddress((void**)&kvb, g_kv);
    cudaGetSymbolAddress((void**)&ob,  g_o);
    cudaGetSymbolAddress((void**)&xh,  g_xh);
    cudaGetSymbolAddress((void**)&xl,  g_xl);
    cudaGetSymbolAddress((void**)&yh,  g_yh);
    cudaGetSymbolAddress((void**)&yl,  g_yl);
    cudaGetSymbolAddress((void**)&qh,  g_qh);
    cudaGetSymbolAddress((void**)&ql,  g_ql);
    cudaGetSymbolAddress((void**)&kvh, g_kvh);
    cudaGetSymbolAddress((void**)&kvl, g_kvl);
    cudaGetSymbolAddress((void**)&xrh, g_xrh);
    cudaGetSymbolAddress((void**)&xrl, g_xrl);
    cudaGetSymbolAddress((void**)&wqh, g_wqt_h);
    cudaGetSymbolAddress((void**)&wql, g_wqt_l);
    cudaGetSymbolAddress((void**)&wkvh, g_wkvt_h);
    cudaGetSymbolAddress((void**)&wkvl, g_wkvt_l);
    cudaGetSymbolAddress((void**)&wph, g_wpt_h);
    cudaGetSymbolAddress((void**)&wpl, g_wpt_l);

    cudaFuncSetAttribute(attn_mma_kernel, cudaFuncAttributeMaxDynamicSharedMemorySize, ATT2_SMEM);

    int nx = BATCH * NTOK * CDIM;
    split_kernel<<<(nx + 255) / 256, 256>>>(x, xh, xl, nx);
    wsplit_t_kernel<<<dim3(512 / 32, 512 / 32), 256>>>(Wq, wqh, wql, 512, 512);
    wsplit_t_kernel<<<dim3(1024 / 32, 512 / 32), 256>>>(Wkv, wkvh, wkvl, 512, 1024);
    wsplit_t_kernel<<<dim3(512 / 32, 512 / 32), 256>>>(Wp, wph, wpl, 512, 512);

    conv_ln_kernel<<<BATCH * NSR, 256>>>(x, srw, srb, srg, srbeta, xrh, xrl);

    // kv = xr @ Wkv + bkv   -> f32 (for upsample) + bf16 hi/lo (for attention)
    gemm_mma_kernel<<<dim3(1024 / 128, (BATCH * NSR + 127) / 128), 256>>>(
        xrh, xrl, wkvh, wkvl, bkv, kvb, kvh, kvl, BATCH * NSR, 1024);
    // q = x @ Wq + bq       -> bf16 hi/lo only
    gemm_mma_kernel<<<dim3(512 / 128, (BATCH * NTOK) / 128), 256>>>(
        xh, xl, wqh, wql, bq, (float*)nullptr, qh, ql, BATCH * NTOK, 512);

    // attention on tensor cores
    attn_mma_kernel<<<dim3(NTOK / 64, BATCH * NHEADS), 128, ATT2_SMEM>>>(qh, ql, kvh, kvl, ob);

    ups_ln_add_kernel<<<BATCH * NTOK, 256>>>(kvb, ob, upg, upbeta, yh, yl);

    // out = y @ Wp + bp     -> f32
    gemm_mma_kernel<<<dim3(512 / 128, (BATCH * NTOK) / 128), 256>>>(
        yh, yl, wph, wpl, bp, out, (__nv_bfloat16*)nullptr, (__nv_bfloat16*)nullptr,
        BATCH * NTOK, 512);
}